// round 16
// baseline (speedup 1.0000x reference)
#include <cuda_runtime.h>
#include <cuda_bf16.h>
#include <math.h>
#include <stdint.h>

#define BB 32
#define SS 1024
#define HH 768
#define EE 128
#define WW 8
#define PP 512
#define NTT 5
#define NRR 9
#define DD1 128
#define HEADS1 2
#define DD2 64
#define RDD 32
#define F1 256  // HEADS1*DD1

// ---------------- scratch ----------------
static __device__ float g_x0[BB*EE*HH];
static __device__ float g_h1[BB*EE*F1];
static __device__ float g_s1[BB*HEADS1*EE];
static __device__ float g_d1[BB*HEADS1*EE];
static __device__ float g_o1[BB*EE*F1];
static __device__ float g_x1[BB*EE*F1];
static __device__ float g_x2[BB*EE*DD2];
static __device__ float g_p[BB*EE*512];      // [row][512] = [p1|p2]
static __device__ float g_cls[BB*256];
static __device__ float g_rel[NRR*256];
// packed bf16 hi/lo weights (pairs along K)
static __device__ uint32_t g_W1H[(HH/2)*F1], g_W1L[(HH/2)*F1];      // 384x256
static __device__ uint32_t g_W2H[(F1/2)*DD2], g_W2L[(F1/2)*DD2];    // 128x64
static __device__ uint32_t g_WpH[(DD2/2)*512], g_WpL[(DD2/2)*512];  // 32x512

// ---------------- helpers ----------------
__device__ __forceinline__ void split2(float v0, float v1, uint32_t& h, uint32_t& l) {
    uint32_t hp, lp;
    asm("cvt.rn.bf16x2.f32 %0, %1, %2;" : "=r"(hp) : "f"(v1), "f"(v0));
    float h0 = __uint_as_float(hp << 16);
    float h1 = __uint_as_float(hp & 0xffff0000u);
    asm("cvt.rn.bf16x2.f32 %0, %1, %2;" : "=r"(lp) : "f"(v1 - h1), "f"(v0 - h0));
    h = hp; l = lp;
}
__device__ __forceinline__ void mma16(float* d, const uint32_t* a, const uint32_t* b) {
    asm volatile(
        "mma.sync.aligned.m16n8k16.row.col.f32.bf16.bf16.f32 "
        "{%0,%1,%2,%3},{%4,%5,%6,%7},{%8,%9},{%0,%1,%2,%3};"
        : "+f"(d[0]), "+f"(d[1]), "+f"(d[2]), "+f"(d[3])
        : "r"(a[0]), "r"(a[1]), "r"(a[2]), "r"(a[3]), "r"(b[0]), "r"(b[1]));
}

// ---------------- stage0: prep + zero + pool + misc (one launch) ----------------
#define NB_PREP 480
#define NB_ZERO 64
#define NB_POOL (BB*EE)
#define NB_MISC (BB + NRR)
#define B_ZERO  NB_PREP
#define B_POOL  (B_ZERO + NB_ZERO)
#define B_MISC  (B_POOL + NB_POOL)
#define NB_STAGE0 (B_MISC + NB_MISC)

__global__ __launch_bounds__(256) void stage0_kernel(
        const float* __restrict__ seq,
        const int* __restrict__ starts,
        const int* __restrict__ type_ids,
        const float* __restrict__ temb,
        const float* __restrict__ remb,
        const float* __restrict__ W1,
        const float* __restrict__ W2,
        const float* __restrict__ Wr1,
        const float* __restrict__ br1) {
    __shared__ float4 sbuf4[1730];          // 27.7 KB, aliased per branch
    float* sbuf = (float*)sbuf4;
    int blk = blockIdx.x;
    int t = threadIdx.x;

    if (blk < NB_PREP) {
        int idx = blk*256 + t;
        if (idx < 98304) {
            int kp = idx >> 8, n = idx & 255;
            uint32_t h, l;
            split2(W1[(size_t)(2*kp)*F1 + n], W1[(size_t)(2*kp+1)*F1 + n], h, l);
            g_W1H[idx] = h; g_W1L[idx] = l;
        } else if (idx < 106496) {
            int j = idx - 98304;
            int kp = j >> 6, n = j & 63;
            uint32_t h, l;
            split2(W2[(size_t)(2*kp)*DD2 + n], W2[(size_t)(2*kp+1)*DD2 + n], h, l);
            g_W2H[j] = h; g_W2L[j] = l;
        } else {
            int j = idx - 106496;
            int kp = j >> 9, n = j & 511;
            int col = n & 255;
            int base = (n < 256) ? 0 : 64;
            uint32_t h, l;
            split2(Wr1[(size_t)(base + 2*kp)*256 + col],
                   Wr1[(size_t)(base + 2*kp + 1)*256 + col], h, l);
            g_WpH[j] = h; g_WpL[j] = l;
        }
    } else if (blk < B_POOL) {
        // ---- zero s1/d1 accumulators ----
        int j = (blk - B_ZERO)*256 + t;
        if (j < 8192) g_s1[j] = 0.f;
        else g_d1[j - 8192] = 0.f;
    } else if (blk < B_MISC) {
        // ---- entity pooling + type embedding ----
        int be = blk - B_POOL;
        int b = be >> 7;
        float* toks = sbuf;
        float* colsum = sbuf + WW*HH;
        float* logits = sbuf + WW*HH + HH;

        int start = starts[be];
        const float4* base4 = (const float4*)(seq + ((size_t)b*SS + start)*HH);
        #pragma unroll
        for (int i = 0; i < 6; i++) sbuf4[t + i*256] = base4[t + i*256];
        __syncthreads();

        for (int h = t; h < HH; h += 256) {
            float cs = 0.f;
            #pragma unroll
            for (int w = 0; w < WW; w++) cs += toks[w*HH + h];
            colsum[h] = cs;
        }
        __syncthreads();

        int warp = t >> 5, lane = t & 31;
        {
            float acc = 0.f;
            for (int h = lane; h < HH; h += 32) acc += toks[warp*HH + h] * colsum[h];
            #pragma unroll
            for (int off = 16; off > 0; off >>= 1) acc += __shfl_xor_sync(0xffffffffu, acc, off);
            if (lane == 0) logits[warp] = acc * 0.125f;
        }
        __syncthreads();

        float m = logits[0];
        #pragma unroll
        for (int w = 1; w < WW; w++) m = fmaxf(m, logits[w]);
        float ex[WW]; float sum = 0.f;
        #pragma unroll
        for (int w = 0; w < WW; w++) { ex[w] = __expf(logits[w] - m); sum += ex[w]; }
        float inv = 1.f / sum;

        int type = type_ids[be];
        const float* te = temb + (size_t)type*HH;
        for (int h = t; h < HH; h += 256) {
            float p = 0.f;
            #pragma unroll
            for (int w = 0; w < WW; w++) p += ex[w] * toks[w*HH + h];
            g_x0[(size_t)be*HH + h] = p*inv + te[h];
        }
    } else {
        // ---- cls (+br1) / rel projections ----
        int mblk = blk - B_MISC;
        int c = t;
        if (mblk < BB) {
            int b = mblk;
            float* cls = sbuf;
            for (int h = c; h < HH; h += 256) cls[h] = seq[(size_t)b*SS*HH + h];
            __syncthreads();
            float acc = br1[c];
            const float* w = Wr1 + (size_t)160*256 + c;
            for (int h = 0; h < HH; h++) acc += cls[h] * w[(size_t)h*256];
            g_cls[b*256 + c] = acc;
        } else {
            int r = mblk - BB;
            float* rv = sbuf;
            if (c < RDD) rv[c] = remb[r*RDD + c];
            __syncthreads();
            float acc = 0.f;
            #pragma unroll
            for (int k = 0; k < RDD; k++) acc += rv[k] * Wr1[(size_t)(128 + k)*256 + c];
            g_rel[r*256 + c] = acc;
        }
    }
}

#define SA 20   // A smem stride (u32)
#define SBp 72  // B smem stride (u32)

// ---------------- GEMM with pre-packed B; double-buffered smem; s/d epilogue ------
__global__ __launch_bounds__(256) void bf16_gemm_pb(
        const float* __restrict__ A,
        const uint32_t* __restrict__ BH, const uint32_t* __restrict__ BL,
        float* __restrict__ C, int M, int N, int K, int lda,
        const float* __restrict__ a_src, const float* __restrict__ a_dst,
        float* __restrict__ s_out, float* __restrict__ d_out,
        int D, int Hh) {
    __shared__ uint32_t AsH[2][64][SA], AsL[2][64][SA];
    __shared__ uint32_t BsH[2][16][SBp], BsL[2][16][SBp];

    int tid = threadIdx.x;
    int wid = tid >> 5, lane = tid & 31;
    int g = lane >> 2, ti = lane & 3;
    int warp_m = wid >> 2, warp_n = wid & 3;
    int m0 = blockIdx.y * 64, n0 = blockIdx.x * 64;

    int ar = tid >> 3, aq = tid & 7;
    int br = tid >> 4, bn = (tid & 15) * 4;

    const float* Ap0 = A + (size_t)(m0 + ar)*lda + aq*4;
    const float* Ap1 = A + (size_t)(m0 + ar + 32)*lda + aq*4;
    const uint32_t* Bbase = BH + (size_t)br*N + n0 + bn;
    const uint32_t* Lbase = BL + (size_t)br*N + n0 + bn;

    float4 a0 = *(const float4*)Ap0;
    float4 a1 = *(const float4*)Ap1;
    uint4 bhv = *(const uint4*)Bbase;
    uint4 blv = *(const uint4*)Lbase;

    {
        uint32_t h0, l0, h1, l1;
        split2(a0.x, a0.y, h0, l0);
        split2(a0.z, a0.w, h1, l1);
        AsH[0][ar][2*aq]   = h0; AsH[0][ar][2*aq+1] = h1;
        AsL[0][ar][2*aq]   = l0; AsL[0][ar][2*aq+1] = l1;
        split2(a1.x, a1.y, h0, l0);
        split2(a1.z, a1.w, h1, l1);
        AsH[0][ar+32][2*aq]   = h0; AsH[0][ar+32][2*aq+1] = h1;
        AsL[0][ar+32][2*aq]   = l0; AsL[0][ar+32][2*aq+1] = l1;
        *(uint4*)&BsH[0][br][bn] = bhv;
        *(uint4*)&BsL[0][br][bn] = blv;
    }
    __syncthreads();

    float acc[2][2][4] = {};
    int nch = K >> 5;

    for (int ic = 0; ic < nch; ic++) {
        int cur = ic & 1;
        bool more = (ic + 1 < nch);
        if (more) {
            int kc = (ic + 1) * 32;
            a0 = *(const float4*)(Ap0 + kc);
            a1 = *(const float4*)(Ap1 + kc);
            size_t off = (size_t)(kc >> 1)*N;
            bhv = *(const uint4*)(Bbase + off);
            blv = *(const uint4*)(Lbase + off);
        }

        #pragma unroll
        for (int s = 0; s < 2; s++) {
            int ab = s*8;
            uint32_t aH[2][4], aL[2][4], bH[2][2], bL[2][2];
            #pragma unroll
            for (int mt = 0; mt < 2; mt++) {
                int rm = warp_m*32 + mt*16;
                aH[mt][0] = AsH[cur][rm + g    ][ab + ti    ];
                aH[mt][1] = AsH[cur][rm + g + 8][ab + ti    ];
                aH[mt][2] = AsH[cur][rm + g    ][ab + ti + 4];
                aH[mt][3] = AsH[cur][rm + g + 8][ab + ti + 4];
                aL[mt][0] = AsL[cur][rm + g    ][ab + ti    ];
                aL[mt][1] = AsL[cur][rm + g + 8][ab + ti    ];
                aL[mt][2] = AsL[cur][rm + g    ][ab + ti + 4];
                aL[mt][3] = AsL[cur][rm + g + 8][ab + ti + 4];
            }
            #pragma unroll
            for (int nt = 0; nt < 2; nt++) {
                int cn = warp_n*16 + nt*8;
                bH[nt][0] = BsH[cur][ab + ti    ][cn + g];
                bH[nt][1] = BsH[cur][ab + ti + 4][cn + g];
                bL[nt][0] = BsL[cur][ab + ti    ][cn + g];
                bL[nt][1] = BsL[cur][ab + ti + 4][cn + g];
            }
            #pragma unroll
            for (int mt = 0; mt < 2; mt++)
                #pragma unroll
                for (int nt = 0; nt < 2; nt++) {
                    mma16(acc[mt][nt], aH[mt], bL[nt]);
                    mma16(acc[mt][nt], aL[mt], bH[nt]);
                    mma16(acc[mt][nt], aH[mt], bH[nt]);
                }
        }

        if (more) {
            int nxt = cur ^ 1;
            uint32_t h0, l0, h1, l1;
            split2(a0.x, a0.y, h0, l0);
            split2(a0.z, a0.w, h1, l1);
            AsH[nxt][ar][2*aq]   = h0; AsH[nxt][ar][2*aq+1] = h1;
            AsL[nxt][ar][2*aq]   = l0; AsL[nxt][ar][2*aq+1] = l1;
            split2(a1.x, a1.y, h0, l0);
            split2(a1.z, a1.w, h1, l1);
            AsH[nxt][ar+32][2*aq]   = h0; AsH[nxt][ar+32][2*aq+1] = h1;
            AsL[nxt][ar+32][2*aq]   = l0; AsL[nxt][ar+32][2*aq+1] = l1;
            *(uint4*)&BsH[nxt][br][bn] = bhv;
            *(uint4*)&BsL[nxt][br][bn] = blv;
        }
        __syncthreads();
    }

    #pragma unroll
    for (int mt = 0; mt < 2; mt++) {
        int rm = m0 + warp_m*32 + mt*16;
        #pragma unroll
        for (int nt = 0; nt < 2; nt++) {
            int cn = n0 + warp_n*16 + nt*8;
            float* c0 = C + (size_t)(rm + g)*N + cn + 2*ti;
            float* c2 = C + (size_t)(rm + g + 8)*N + cn + 2*ti;
            c0[0] = acc[mt][nt][0]; c0[1] = acc[mt][nt][1];
            c2[0] = acc[mt][nt][2]; c2[1] = acc[mt][nt][3];
        }
    }

    if (D) {
        int head = n0 / D;
        const float* as = a_src + head*D;
        const float* ad = a_dst + head*D;
        int cbase = n0 & (D-1);
        float sv[4] = {0.f,0.f,0.f,0.f}, dv[4] = {0.f,0.f,0.f,0.f};
        #pragma unroll
        for (int nt = 0; nt < 2; nt++) {
            int c = cbase + warp_n*16 + nt*8 + 2*ti;
            float w0s = as[c], w1s = as[c+1];
            float w0d = ad[c], w1d = ad[c+1];
            #pragma unroll
            for (int mt = 0; mt < 2; mt++) {
                sv[mt*2+0] += acc[mt][nt][0]*w0s + acc[mt][nt][1]*w1s;
                sv[mt*2+1] += acc[mt][nt][2]*w0s + acc[mt][nt][3]*w1s;
                dv[mt*2+0] += acc[mt][nt][0]*w0d + acc[mt][nt][1]*w1d;
                dv[mt*2+1] += acc[mt][nt][2]*w0d + acc[mt][nt][3]*w1d;
            }
        }
        #pragma unroll
        for (int i = 0; i < 4; i++) {
            sv[i] += __shfl_xor_sync(0xffffffffu, sv[i], 1);
            sv[i] += __shfl_xor_sync(0xffffffffu, sv[i], 2);
            dv[i] += __shfl_xor_sync(0xffffffffu, dv[i], 1);
            dv[i] += __shfl_xor_sync(0xffffffffu, dv[i], 2);
        }
        if (ti == 0) {
            #pragma unroll
            for (int mt = 0; mt < 2; mt++)
                #pragma unroll
                for (int rr = 0; rr < 2; rr++) {
                    int grow = m0 + warp_m*32 + mt*16 + rr*8 + g;
                    int b = grow >> 7, e = grow & 127;
                    int idx = (b*Hh + head)*EE + e;
                    atomicAdd(&s_out[idx], sv[mt*2+rr]);
                    atomicAdd(&d_out[idx], dv[mt*2+rr]);
                }
        }
    }
}

// ---------------- attention GEMM (attn1 only): C = softmax(leaky(d+s)) @ B --------
__global__ __launch_bounds__(256) void attn_gemm(
        const float* __restrict__ s_in, const float* __restrict__ d_in,
        const float* __restrict__ Bm, float* __restrict__ C,
        int N, int ldb, int ldc,
        int Hh, long sBb, long sBh, long sCb, long sCh) {
    int bz = blockIdx.z;
    int bb = bz / Hh, hh = bz - bb*Hh;
    const float* sp = s_in + (size_t)bz*EE;
    const float* dp = d_in + (size_t)bz*EE;
    Bm += (long)bb * sBb + (long)hh * sBh;
    C  += (long)bb * sCb + (long)hh * sCh;

    __shared__ uint32_t AsH[2][64][SA], AsL[2][64][SA];
    __shared__ uint32_t BsH[2][16][SBp], BsL[2][16][SBp];
    __shared__ float s_sh[EE], d_sh[64], m_sh[64], inv_sh[64];

    int tid = threadIdx.x;
    int wid = tid >> 5, lane = tid & 31;
    int g = lane >> 2, ti = lane & 3;
    int warp_m = wid >> 2, warp_n = wid & 3;
    int m0 = blockIdx.y * 64, n0 = blockIdx.x * 64;

    int arow = tid >> 3, aq = tid & 7;
    int br = tid >> 4, bn = (tid & 15) * 4;
    const float* Bp0 = Bm + (size_t)(2*br)*ldb + n0 + bn;
    const float* Bp1 = Bm + (size_t)(2*br + 1)*ldb + n0 + bn;

    if (tid < EE) s_sh[tid] = sp[tid];
    else if (tid < EE + 64) d_sh[tid - EE] = dp[m0 + tid - EE];

    float4 b0v = *(const float4*)Bp0;
    float4 b1v = *(const float4*)Bp1;
    __syncthreads();

    #pragma unroll
    for (int rr = 0; rr < 8; rr++) {
        int i = wid*8 + rr;
        float di = d_sh[i];
        float ev[4]; float m = -1e30f;
        #pragma unroll
        for (int q = 0; q < 4; q++) {
            float e = di + s_sh[lane + q*32];
            e = fmaxf(e, 0.2f*e);
            ev[q] = e;
            m = fmaxf(m, e);
        }
        #pragma unroll
        for (int off = 16; off > 0; off >>= 1) m = fmaxf(m, __shfl_xor_sync(0xffffffffu, m, off));
        float sum = 0.f;
        #pragma unroll
        for (int q = 0; q < 4; q++) sum += __expf(ev[q] - m);
        #pragma unroll
        for (int off = 16; off > 0; off >>= 1) sum += __shfl_xor_sync(0xffffffffu, sum, off);
        if (lane == 0) { m_sh[i] = m; inv_sh[i] = 1.f / sum; }
    }
    __syncthreads();

    {
        float di = d_sh[arow], mi = m_sh[arow], ii = inv_sh[arow];
        int row2 = (tid + 256) >> 3;
        float di2 = d_sh[row2], mi2 = m_sh[row2], ii2 = inv_sh[row2];
        float v[4], v2[4];
        #pragma unroll
        for (int tq = 0; tq < 4; tq++) {
            float e = di + s_sh[4*aq + tq];
            e = fmaxf(e, 0.2f*e);
            v[tq] = __expf(e - mi) * ii;
            float e2 = di2 + s_sh[4*aq + tq];
            e2 = fmaxf(e2, 0.2f*e2);
            v2[tq] = __expf(e2 - mi2) * ii2;
        }
        uint32_t h0, l0, h1, l1;
        split2(v[0], v[1], h0, l0);
        split2(v[2], v[3], h1, l1);
        AsH[0][arow][2*aq] = h0; AsH[0][arow][2*aq+1] = h1;
        AsL[0][arow][2*aq] = l0; AsL[0][arow][2*aq+1] = l1;
        split2(v2[0], v2[1], h0, l0);
        split2(v2[2], v2[3], h1, l1);
        AsH[0][row2][2*aq] = h0; AsH[0][row2][2*aq+1] = h1;
        AsL[0][row2][2*aq] = l0; AsL[0][row2][2*aq+1] = l1;
        uint32_t h, l;
        split2(b0v.x, b1v.x, h, l); BsH[0][br][bn+0] = h; BsL[0][br][bn+0] = l;
        split2(b0v.y, b1v.y, h, l); BsH[0][br][bn+1] = h; BsL[0][br][bn+1] = l;
        split2(b0v.z, b1v.z, h, l); BsH[0][br][bn+2] = h; BsL[0][br][bn+2] = l;
        split2(b0v.w, b1v.w, h, l); BsH[0][br][bn+3] = h; BsL[0][br][bn+3] = l;
    }
    __syncthreads();

    float acc[2][2][4] = {};

    #pragma unroll
    for (int ic = 0; ic < 4; ic++) {
        int cur = ic & 1;
        bool more = (ic + 1 < 4);
        if (more) {
            int kc = (ic + 1) * 32;
            b0v = *(const float4*)(Bp0 + (size_t)kc*ldb);
            b1v = *(const float4*)(Bp1 + (size_t)kc*ldb);
        }

        #pragma unroll
        for (int s = 0; s < 2; s++) {
            int ab = s*8;
            uint32_t aH[2][4], aL[2][4], bH[2][2], bL[2][2];
            #pragma unroll
            for (int mt = 0; mt < 2; mt++) {
                int rm = warp_m*32 + mt*16;
                aH[mt][0] = AsH[cur][rm + g    ][ab + ti    ];
                aH[mt][1] = AsH[cur][rm + g + 8][ab + ti    ];
                aH[mt][2] = AsH[cur][rm + g    ][ab + ti + 4];
                aH[mt][3] = AsH[cur][rm + g + 8][ab + ti + 4];
                aL[mt][0] = AsL[cur][rm + g    ][ab + ti    ];
                aL[mt][1] = AsL[cur][rm + g + 8][ab + ti    ];
                aL[mt][2] = AsL[cur][rm + g    ][ab + ti + 4];
                aL[mt][3] = AsL[cur][rm + g + 8][ab + ti + 4];
            }
            #pragma unroll
            for (int nt = 0; nt < 2; nt++) {
                int cn = warp_n*16 + nt*8;
                bH[nt][0] = BsH[cur][ab + ti    ][cn + g];
                bH[nt][1] = BsH[cur][ab + ti + 4][cn + g];
                bL[nt][0] = BsL[cur][ab + ti    ][cn + g];
                bL[nt][1] = BsL[cur][ab + ti + 4][cn + g];
            }
            #pragma unroll
            for (int mt = 0; mt < 2; mt++)
                #pragma unroll
                for (int nt = 0; nt < 2; nt++) {
                    mma16(acc[mt][nt], aH[mt], bL[nt]);
                    mma16(acc[mt][nt], aL[mt], bH[nt]);
                    mma16(acc[mt][nt], aH[mt], bH[nt]);
                }
        }

        if (more) {
            int nxt = cur ^ 1;
            int kc = (ic + 1) * 32;
            float di = d_sh[arow], mi = m_sh[arow], ii = inv_sh[arow];
            int row2 = (tid + 256) >> 3;
            float di2 = d_sh[row2], mi2 = m_sh[row2], ii2 = inv_sh[row2];
            float v[4], v2[4];
            #pragma unroll
            for (int tq = 0; tq < 4; tq++) {
                float e = di + s_sh[kc + 4*aq + tq];
                e = fmaxf(e, 0.2f*e);
                v[tq] = __expf(e - mi) * ii;
                float e2 = di2 + s_sh[kc + 4*aq + tq];
                e2 = fmaxf(e2, 0.2f*e2);
                v2[tq] = __expf(e2 - mi2) * ii2;
            }
            uint32_t h0, l0, h1, l1;
            split2(v[0], v[1], h0, l0);
            split2(v[2], v[3], h1, l1);
            AsH[nxt][arow][2*aq] = h0; AsH[nxt][arow][2*aq+1] = h1;
            AsL[nxt][arow][2*aq] = l0; AsL[nxt][arow][2*aq+1] = l1;
            split2(v2[0], v2[1], h0, l0);
            split2(v2[2], v2[3], h1, l1);
            AsH[nxt][row2][2*aq] = h0; AsH[nxt][row2][2*aq+1] = h1;
            AsL[nxt][row2][2*aq] = l0; AsL[nxt][row2][2*aq+1] = l1;
            uint32_t h, l;
            split2(b0v.x, b1v.x, h, l); BsH[nxt][br][bn+0] = h; BsL[nxt][br][bn+0] = l;
            split2(b0v.y, b1v.y, h, l); BsH[nxt][br][bn+1] = h; BsL[nxt][br][bn+1] = l;
            split2(b0v.z, b1v.z, h, l); BsH[nxt][br][bn+2] = h; BsL[nxt][br][bn+2] = l;
            split2(b0v.w, b1v.w, h, l); BsH[nxt][br][bn+3] = h; BsL[nxt][br][bn+3] = l;
        }
        __syncthreads();
    }

    #pragma unroll
    for (int mt = 0; mt < 2; mt++) {
        int rm = m0 + warp_m*32 + mt*16;
        #pragma unroll
        for (int nt = 0; nt < 2; nt++) {
            int cn = n0 + warp_n*16 + nt*8;
            float* c0 = C + (size_t)(rm + g)*ldc + cn + 2*ti;
            float* c2 = C + (size_t)(rm + g + 8)*ldc + cn + 2*ti;
            c0[0] = acc[mt][nt][0]; c0[1] = acc[mt][nt][1];
            c2[0] = acc[mt][nt][2]; c2[1] = acc[mt][nt][3];
        }
    }
}

// ---------------- bias + layernorm + elu (256-wide rows), warp-per-row ----------------
__global__ void ln256_kernel(const float* __restrict__ in,
                             const float* __restrict__ bias,
                             const float* __restrict__ g,
                             const float* __restrict__ bt,
                             float* __restrict__ out) {
    int t = threadIdx.x;
    int row = blockIdx.x*8 + (t >> 5);
    int lane = t & 31;
    int c0 = 4*lane, c1 = 128 + 4*lane;
    const float* ir = in + (size_t)row*256;
    float4 v0 = *(const float4*)(ir + c0);
    float4 v1 = *(const float4*)(ir + c1);
    float4 b0 = *(const float4*)(bias + c0);
    float4 b1 = *(const float4*)(bias + c1);
    v0.x += b0.x; v0.y += b0.y; v0.z += b0.z; v0.w += b0.w;
    v1.x += b1.x; v1.y += b1.y; v1.z += b1.z; v1.w += b1.w;
    float s  = v0.x+v0.y+v0.z+v0.w + v1.x+v1.y+v1.z+v1.w;
    float s2 = v0.x*v0.x+v0.y*v0.y+v0.z*v0.z+v0.w*v0.w
             + v1.x*v1.x+v1.y*v1.y+v1.z*v1.z+v1.w*v1.w;
    #pragma unroll
    for (int off = 16; off > 0; off >>= 1) {
        s  += __shfl_xor_sync(0xffffffffu, s,  off);
        s2 += __shfl_xor_sync(0xffffffffu, s2, off);
    }
    float mean = s * (1.f/256.f);
    float var  = s2 * (1.f/256.f) - mean*mean;
    float r = rsqrtf(var + 1e-5f);
    float4 g0 = *(const float4*)(g + c0);
    float4 g1 = *(const float4*)(g + c1);
    float4 t0 = *(const float4*)(bt + c0);
    float4 t1 = *(const float4*)(bt + c1);
    float4 o0, o1;
    o0.x = (v0.x-mean)*r*g0.x + t0.x; o0.y = (v0.y-mean)*r*g0.y + t0.y;
    o0.z = (v0.z-mean)*r*g0.z + t0.z; o0.w = (v0.w-mean)*r*g0.w + t0.w;
    o1.x = (v1.x-mean)*r*g1.x + t1.x; o1.y = (v1.y-mean)*r*g1.y + t1.y;
    o1.z = (v1.z-mean)*r*g1.z + t1.z; o1.w = (v1.w-mean)*r*g1.w + t1.w;
    o0.x = o0.x > 0.f ? o0.x : expm1f(o0.x); o0.y = o0.y > 0.f ? o0.y : expm1f(o0.y);
    o0.z = o0.z > 0.f ? o0.z : expm1f(o0.z); o0.w = o0.w > 0.f ? o0.w : expm1f(o0.w);
    o1.x = o1.x > 0.f ? o1.x : expm1f(o1.x); o1.y = o1.y > 0.f ? o1.y : expm1f(o1.y);
    o1.z = o1.z > 0.f ? o1.z : expm1f(o1.z); o1.w = o1.w > 0.f ? o1.w : expm1f(o1.w);
    float* orow = out + (size_t)row*256;
    *(float4*)(orow + c0) = o0;
    *(float4*)(orow + c1) = o1;
}

// ---------------- tail kernel: per-batch h2 + s2/d2 + softmax + attn2 + LN2 ------
// grid = BB blocks (one per batch), 256 threads, dynamic smem.
#define TS_ASH   0
#define TS_ASL   10240
#define TS_BSH   20480
#define TS_BSL   25088
#define TS_H2H   29696
#define TS_H2L   48128
#define TS_H2F   66560            // [128][68] floats (also LN Cs)
#define TS_STAT  101376           // s,d,m,inv : 4 x 128 floats
#define SMEM_TAIL (101376 + 2048)

__global__ __launch_bounds__(256) void tail_kernel(
        const float* __restrict__ x1,
        const uint32_t* __restrict__ W2H, const uint32_t* __restrict__ W2L,
        const float* __restrict__ a_src2, const float* __restrict__ a_dst2,
        const float* __restrict__ b2, const float* __restrict__ lng,
        const float* __restrict__ lnt, float* __restrict__ x2) {
    extern __shared__ char smem[];
    uint32_t* AsH = (uint32_t*)(smem + TS_ASH);   // [128][20]
    uint32_t* AsL = (uint32_t*)(smem + TS_ASL);
    uint32_t* BsH = (uint32_t*)(smem + TS_BSH);   // [16][72]
    uint32_t* BsL = (uint32_t*)(smem + TS_BSL);
    uint32_t* H2H = (uint32_t*)(smem + TS_H2H);   // [64][72]
    uint32_t* H2L = (uint32_t*)(smem + TS_H2L);
    float*    H2f = (float*)(smem + TS_H2F);      // [128][68]
    float*    s_sh = (float*)(smem + TS_STAT);
    float*    d_sh = s_sh + 128;
    float*    m_sh = d_sh + 128;
    float*    inv_sh = m_sh + 128;

    int tid = threadIdx.x;
    int wid = tid >> 5, lane = tid & 31;
    int g = lane >> 2, ti = lane & 3;
    int warp_m = wid >> 2, warp_n = wid & 3;   // warp_m in {0,1} -> 64 rows each
    int b = blockIdx.x;

    const float* Ab = x1 + (size_t)b*EE*F1;    // [128][256]
    int aq = tid & 7;
    int arA = tid >> 3;                         // base row (0..31); rows arA + 32*i
    int br = tid >> 4, bn = (tid & 15) * 4;    // B: kpair row, cols

    // ================= GEMM1: h2 = x1_b @ W2 (M=128,N=64,K=256) =================
    float4 a[4];
    uint4 bhv, blv;
    #pragma unroll
    for (int i = 0; i < 4; i++)
        a[i] = *(const float4*)(Ab + (size_t)(arA + 32*i)*F1 + aq*4);
    bhv = *(const uint4*)(W2H + (size_t)br*DD2 + bn);
    blv = *(const uint4*)(W2L + (size_t)br*DD2 + bn);

    float acc[4][2][4] = {};

    #pragma unroll
    for (int ic = 0; ic < 8; ic++) {
        // stage current chunk
        #pragma unroll
        for (int i = 0; i < 4; i++) {
            int row = arA + 32*i;
            uint32_t h0, l0, h1, l1;
            split2(a[i].x, a[i].y, h0, l0);
            split2(a[i].z, a[i].w, h1, l1);
            AsH[row*SA + 2*aq]   = h0; AsH[row*SA + 2*aq+1] = h1;
            AsL[row*SA + 2*aq]   = l0; AsL[row*SA + 2*aq+1] = l1;
        }
        *(uint4*)&BsH[br*SBp + bn] = bhv;
        *(uint4*)&BsL[br*SBp + bn] = blv;
        __syncthreads();

        if (ic + 1 < 8) {
            int kc = (ic + 1) * 32;
            #pragma unroll
            for (int i = 0; i < 4; i++)
                a[i] = *(const float4*)(Ab + (size_t)(arA + 32*i)*F1 + kc + aq*4);
            bhv = *(const uint4*)(W2H + (size_t)((ic+1)*16 + br)*DD2 + bn);
            blv = *(const uint4*)(W2L + (size_t)((ic+1)*16 + br)*DD2 + bn);
        }

        #pragma unroll
        for (int s = 0; s < 2; s++) {
            int ab = s*8;
            uint32_t aH[4][4], aL[4][4], bH[2][2], bL[2][2];
            #pragma unroll
            for (int mt = 0; mt < 4; mt++) {
                int rm = warp_m*64 + mt*16;
                aH[mt][0] = AsH[(rm + g    )*SA + ab + ti    ];
                aH[mt][1] = AsH[(rm + g + 8)*SA + ab + ti    ];
                aH[mt][2] = AsH[(rm + g    )*SA + ab + ti + 4];
                aH[mt][3] = AsH[(rm + g + 8)*SA + ab + ti + 4];
                aL[mt][0] = AsL[(rm + g    )*SA + ab + ti    ];
                aL[mt][1] = AsL[(rm + g + 8)*SA + ab + ti    ];
                aL[mt][2] = AsL[(rm + g    )*SA + ab + ti + 4];
                aL[mt][3] = AsL[(rm + g + 8)*SA + ab + ti + 4];
            }
            #pragma unroll
            for (int nt = 0; nt < 2; nt++) {
                int cn = warp_n*16 + nt*8;
                bH[nt][0] = BsH[(ab + ti    )*SBp + cn + g];
                bH[nt][1] = BsH[(ab + ti + 4)*SBp + cn + g];
                bL[nt][0] = BsL[(ab + ti    )*SBp + cn + g];
                bL[nt][1] = BsL[(ab + ti + 4)*SBp + cn + g];
            }
            #pragma unroll
            for (int mt = 0; mt < 4; mt++)
                #pragma unroll
                for (int nt = 0; nt < 2; nt++) {
                    mma16(acc[mt][nt], aH[mt], bL[nt]);
                    mma16(acc[mt][nt], aL[mt], bH[nt]);
                    mma16(acc[mt][nt], aH[mt], bH[nt]);
                }
        }
        __syncthreads();
    }

    // write h2 (fp32) to H2f
    #pragma unroll
    for (int mt = 0; mt < 4; mt++) {
        int r0 = warp_m*64 + mt*16 + g;
        #pragma unroll
        for (int nt = 0; nt < 2; nt++) {
            int cn = warp_n*16 + nt*8 + 2*ti;
            H2f[r0*68 + cn]     = acc[mt][nt][0];
            H2f[r0*68 + cn + 1] = acc[mt][nt][1];
            H2f[(r0+8)*68 + cn]     = acc[mt][nt][2];
            H2f[(r0+8)*68 + cn + 1] = acc[mt][nt][3];
        }
    }
    __syncthreads();

    // ======== s2/d2 dots (exact fp32) + pack h2 to bf16 hi/lo B operand =========
    {
        float2 asv = *(const float2*)(a_src2 + 2*lane);
        float2 adv = *(const float2*)(a_dst2 + 2*lane);
        #pragma unroll
        for (int rr = 0; rr < 16; rr++) {
            int row = wid*16 + rr;
            float v0 = H2f[row*68 + 2*lane];
            float v1 = H2f[row*68 + 2*lane + 1];
            float s = v0*asv.x + v1*asv.y;
            float d = v0*adv.x + v1*adv.y;
            #pragma unroll
            for (int off = 16; off > 0; off >>= 1) {
                s += __shfl_xor_sync(0xffffffffu, s, off);
                d += __shfl_xor_sync(0xffffffffu, d, off);
            }
            if (lane == 0) { s_sh[row] = s; d_sh[row] = d; }
        }
        #pragma unroll
        for (int i = 0; i < 16; i++) {
            int idx = tid + i*256;
            int kp = idx >> 6, n = idx & 63;
            uint32_t h, l;
            split2(H2f[(2*kp)*68 + n], H2f[(2*kp+1)*68 + n], h, l);
            H2H[kp*SBp + n] = h;
            H2L[kp*SBp + n] = l;
        }
    }
    __syncthreads();

    // ================= softmax stats over 128 rows =================
    #pragma unroll
    for (int rr = 0; rr < 16; rr++) {
        int i = wid*16 + rr;
        float di = d_sh[i];
        float ev[4]; float m = -1e30f;
        #pragma unroll
        for (int q = 0; q < 4; q++) {
            float e = di + s_sh[lane + q*32];
            e = fmaxf(e, 0.2f*e);
            ev[q] = e;
            m = fmaxf(m, e);
        }
        #pragma unroll
        for (int off = 16; off > 0; off >>= 1) m = fmaxf(m, __shfl_xor_sync(0xffffffffu, m, off));
        float sum = 0.f;
        #pragma unroll
        for (int q = 0; q < 4; q++) sum += __expf(ev[q] - m);
        #pragma unroll
        for (int off = 16; off > 0; off >>= 1) sum += __shfl_xor_sync(0xffffffffu, sum, off);
        if (lane == 0) { m_sh[i] = m; inv_sh[i] = 1.f / sum; }
    }
    __syncthreads();

    // ================= GEMM2: o2 = alpha @ h2 (M=128,N=64,K=128) =================
    float acc2[4][2][4] = {};

    #pragma unroll
    for (int ic = 0; ic < 4; ic++) {
        int kc = ic*32;
        // stage alpha chunk (128 x 32)
        #pragma unroll
        for (int i = 0; i < 4; i++) {
            int idx = tid + i*256;
            int row = idx >> 3, q = idx & 7;
            float di = d_sh[row], mi = m_sh[row], ii = inv_sh[row];
            float v[4];
            #pragma unroll
            for (int tq = 0; tq < 4; tq++) {
                float e = di + s_sh[kc + 4*q + tq];
                e = fmaxf(e, 0.2f*e);
                v[tq] = __expf(e - mi) * ii;
            }
            uint32_t h0, l0, h1, l1;
            split2(v[0], v[1], h0, l0);
            split2(v[2], v[3], h1, l1);
            AsH[row*SA + 2*q]   = h0; AsH[row*SA + 2*q+1] = h1;
            AsL[row*SA + 2*q]   = l0; AsL[row*SA + 2*q+1] = l1;
        }
        __syncthreads();

        #pragma unroll
        for (int s = 0; s < 2; s++) {
            int ab = s*8;
            uint32_t aH[4][4], aL[4][4], bH[2][2], bL[2][2];
            #pragma unroll
            for (int mt = 0; mt < 4; mt++) {
                int rm = warp_m*64 + mt*16;
                aH[mt][0] = AsH[(rm + g    )*SA + ab + ti    ];
                aH[mt][1] = AsH[(rm + g + 8)*SA + ab + ti    ];
                aH[mt][2] = AsH[(rm + g    )*SA + ab + ti + 4];
                aH[mt][3] = AsH[(rm + g + 8)*SA + ab + ti + 4];
                aL[mt][0] = AsL[(rm + g    )*SA + ab + ti    ];
                aL[mt][1] = AsL[(rm + g + 8)*SA + ab + ti    ];
                aL[mt][2] = AsL[(rm + g    )*SA + ab + ti + 4];
                aL[mt][3] = AsL[(rm + g + 8)*SA + ab + ti + 4];
            }
            #pragma unroll
            for (int nt = 0; nt < 2; nt++) {
                int cn = warp_n*16 + nt*8;
                bH[nt][0] = H2H[(ic*16 + ab + ti    )*SBp + cn + g];
                bH[nt][1] = H2H[(ic*16 + ab + ti + 4)*SBp + cn + g];
                bL[nt][0] = H2L[(ic*16 + ab + ti    )*SBp + cn + g];
                bL[nt][1] = H2L[(ic*16 + ab + ti + 4)*SBp + cn + g];
            }
            #pragma unroll
            for (int mt = 0; mt < 4; mt++)
                #pragma unroll
                for (int nt = 0; nt < 2; nt++) {
                    mma16(acc2[mt][nt], aH[mt], bL[nt]);
                    mma16(acc2[mt][nt], aL[mt], bH[nt]);
                    mma16(acc2[mt][nt], aH[mt], bH[nt]);
                }
        }
        __syncthreads();
    }

    // ================= fused bias + LN + elu -> x2 =================
    #pragma unroll
    for (int mt = 0; mt < 4; mt++) {
        int r0 = warp_m*64 + mt*16 + g;
        #pragma unroll
        for (int nt = 0; nt < 2; nt++) {
            int cn = warp_n*16 + nt*8 + 2*ti;
            H2f[r0*68 + cn]     = acc2[mt][nt][0];
            H2f[r0*68 + cn + 1] = acc2[mt][nt][1];
            H2f[(r0+8)*68 + cn]     = acc2[mt][nt][2];
            H2f[(r0+8)*68 + cn + 1] = acc2[mt][nt][3];
        }
    }
    __syncthreads();

    {
        int c = 2*lane;
        float2 bb2 = *(const float2*)(b2 + c);
        float2 gg  = *(const float2*)(lng + c);
        float2 tt  = *(const float2*)(lnt + c);
        #pragma unroll
        for (int rr = 0; rr < 16; rr++) {
            int r = wid*16 + rr;
            float vx = H2f[r*68 + c]     + bb2.x;
            float vy = H2f[r*68 + c + 1] + bb2.y;
            float s = vx + vy, s2 = vx*vx + vy*vy;
            #pragma unroll
            for (int off = 16; off > 0; off >>= 1) {
                s  += __shfl_xor_sync(0xffffffffu, s,  off);
                s2 += __shfl_xor_sync(0xffffffffu, s2, off);
            }
            float mean = s * (1.f/64.f);
            float var  = s2 * (1.f/64.f) - mean*mean;
            float rstd = rsqrtf(var + 1e-5f);
            float ox = (vx - mean)*rstd*gg.x + tt.x;
            float oy = (vy - mean)*rstd*gg.y + tt.y;
            ox = ox > 0.f ? ox : expm1f(ox);
            oy = oy > 0.f ? oy : expm1f(oy);
            float2 o2v = make_float2(ox, oy);
            *(float2*)(x2 + (size_t)(b*EE + r)*64 + c) = o2v;
        }
    }
}

// ---------------- final pair scores ----------------
__global__ void pair_kernel(const int* __restrict__ pidx,
                            const int* __restrict__ rids,
                            const float* __restrict__ p,
                            const float* __restrict__ relp,
                            const float* __restrict__ clsp,
                            const float* __restrict__ Wr2,
                            const float* __restrict__ br2,
                            float* __restrict__ out) {
    int g = (blockIdx.x * blockDim.x + threadIdx.x) >> 5;
    int lane = threadIdx.x & 31;
    int b = g / PP, pp = g % PP;
    int pi = pidx[(b*PP + pp)*2 + 0];
    int pj = pidx[(b*PP + pp)*2 + 1];
    int r  = rids[b*PP + pp];
    const float* a1 = p + (size_t)(b*EE + pi)*512;
    const float* a2 = p + (size_t)(b*EE + pj)*512 + 256;
    const float* ar = relp + r*256;
    const float* ac = clsp + b*256;
    float acc = 0.f;
    #pragma unroll
    for (int q = 0; q < 8; q++) {
        int c = lane + q*32;
        float v = a1[c] + a2[c] + ar[c] + ac[c];
        v = fmaxf(v, 0.f);
        acc += v * Wr2[c];
    }
    #pragma unroll
    for (int off = 16; off > 0; off >>= 1) acc += __shfl_xor_sync(0xffffffffu, acc, off);
    if (lane == 0) out[b*PP + pp] = acc + br2[0];
}

// ---------------- launch ----------------
extern "C" void kernel_launch(void* const* d_in, const int* in_sizes, int n_in,
                              void* d_out, int out_size) {
    const float* seq      = (const float*)d_in[0];
    const int*   starts   = (const int*)  d_in[1];
    const int*   type_ids = (const int*)  d_in[2];
    const int*   pair_idx = (const int*)  d_in[3];
    const int*   rel_ids  = (const int*)  d_in[4];
    const float* temb     = (const float*)d_in[5];
    const float* remb     = (const float*)d_in[6];
    const float* W1       = (const float*)d_in[7];
    const float* a_src1   = (const float*)d_in[8];
    const float* a_dst1   = (const float*)d_in[9];
    const float* b1       = (const float*)d_in[10];
    const float* ln1_g    = (const float*)d_in[11];
    const float* ln1_b    = (const float*)d_in[12];
    const float* W2       = (const float*)d_in[13];
    const float* a_src2   = (const float*)d_in[14];
    const float* a_dst2   = (const float*)d_in[15];
    const float* b2       = (const float*)d_in[16];
    const float* ln2_g    = (const float*)d_in[17];
    const float* ln2_b    = (const float*)d_in[18];
    const float* Wr1      = (const float*)d_in[19];
    const float* br1      = (const float*)d_in[20];
    const float* Wr2      = (const float*)d_in[21];
    const float* br2      = (const float*)d_in[22];
    float* out = (float*)d_out;

    float *x0, *h1, *s1, *d1, *o1, *x1, *x2, *p, *clsp, *relp;
    uint32_t *W1H, *W1L, *W2H, *W2L, *WpH, *WpL;
    cudaGetSymbolAddress((void**)&x0,  g_x0);
    cudaGetSymbolAddress((void**)&h1,  g_h1);
    cudaGetSymbolAddress((void**)&s1,  g_s1);
    cudaGetSymbolAddress((void**)&d1,  g_d1);
    cudaGetSymbolAddress((void**)&o1,  g_o1);
    cudaGetSymbolAddress((void**)&x1,  g_x1);
    cudaGetSymbolAddress((void**)&x2,  g_x2);
    cudaGetSymbolAddress((void**)&p,   g_p);
    cudaGetSymbolAddress((void**)&clsp, g_cls);
    cudaGetSymbolAddress((void**)&relp, g_rel);
    cudaGetSymbolAddress((void**)&W1H, g_W1H);
    cudaGetSymbolAddress((void**)&W1L, g_W1L);
    cudaGetSymbolAddress((void**)&W2H, g_W2H);
    cudaGetSymbolAddress((void**)&W2L, g_W2L);
    cudaGetSymbolAddress((void**)&WpH, g_WpH);
    cudaGetSymbolAddress((void**)&WpL, g_WpL);

    static int smem_set = 0;
    if (!smem_set) {
        cudaFuncSetAttribute(tail_kernel,
                             cudaFuncAttributeMaxDynamicSharedMemorySize, SMEM_TAIL);
        smem_set = 1;
    }

    // 1. stage0: prep + zero + pool + misc
    stage0_kernel<<<NB_STAGE0, 256>>>(seq, starts, type_ids, temb, remb,
                                      W1, W2, Wr1, br1);

    // 2. h1 = x0 @ W1, s1/d1 fused
    bf16_gemm_pb<<<dim3(4, 64), 256>>>(x0, W1H, W1L, h1, BB*EE, F1, HH, HH,
                                       a_src1, a_dst1, s1, d1, DD1, HEADS1);

    // 3. o1 = softmax(leaky(d+s)) @ h1, per (b,head)
    attn_gemm<<<dim3(2, 2, BB*HEADS1), 256>>>(s1, d1, h1, o1,
                                              DD1, F1, F1, HEADS1,
                                              (long)EE*F1, DD1, (long)EE*F1, DD1);

    // 4. x1 = elu(ln(o1 + b1))
    ln256_kernel<<<BB*EE/8, 256>>>(o1, b1, ln1_g, ln1_b, x1);

    // 5. tail: per-batch h2 + s2/d2 + softmax + attn2 + LN2 -> x2
    tail_kernel<<<BB, 256, SMEM_TAIL>>>(x1, W2H, W2L, a_src2, a_dst2,
                                        b2, ln2_g, ln2_b, x2);

    // 6. pair projections: (4096,64)@(64,512) -> p=[p1|p2]
    bf16_gemm_pb<<<dim3(8, 64), 256>>>(x2, WpH, WpL, p, BB*EE, 512, DD2, DD2,
                                       nullptr, nullptr, nullptr, nullptr, 0, 1);

    // 7. pair scores
    pair_kernel<<<(BB*PP)/8, 256>>>(pair_idx, rel_ids, p, relp, clsp,
                                    Wr2, br2, out);
}

// round 17
// speedup vs baseline: 1.2071x; 1.2071x over previous
#include <cuda_runtime.h>
#include <cuda_bf16.h>
#include <math.h>
#include <stdint.h>

#define BB 32
#define SS 1024
#define HH 768
#define EE 128
#define WW 8
#define PP 512
#define NTT 5
#define NRR 9
#define DD1 128
#define HEADS1 2
#define DD2 64
#define RDD 32
#define F1 256  // HEADS1*DD1

// ---------------- scratch ----------------
static __device__ float g_x0[BB*EE*HH];
static __device__ float g_h1[BB*EE*F1];
static __device__ float g_s1[BB*HEADS1*EE];
static __device__ float g_d1[BB*HEADS1*EE];
static __device__ float g_o1[BB*EE*F1];
static __device__ float g_x1[BB*EE*F1];
static __device__ float g_h2[BB*EE*DD2];
static __device__ float g_s2[BB*EE];
static __device__ float g_d2[BB*EE];
static __device__ float g_x2[BB*EE*DD2];
static __device__ float g_p[BB*EE*512];      // [row][512] = [p1|p2]
static __device__ float g_cls[BB*256];
static __device__ float g_rel[NRR*256];
// packed bf16 hi/lo weights (pairs along K)
static __device__ uint32_t g_W1H[(HH/2)*F1], g_W1L[(HH/2)*F1];      // 384x256
static __device__ uint32_t g_W2H[(F1/2)*DD2], g_W2L[(F1/2)*DD2];    // 128x64
static __device__ uint32_t g_WpH[(DD2/2)*512], g_WpL[(DD2/2)*512];  // 32x512

// ---------------- helpers ----------------
__device__ __forceinline__ void split2(float v0, float v1, uint32_t& h, uint32_t& l) {
    uint32_t hp, lp;
    asm("cvt.rn.bf16x2.f32 %0, %1, %2;" : "=r"(hp) : "f"(v1), "f"(v0));
    float h0 = __uint_as_float(hp << 16);
    float h1 = __uint_as_float(hp & 0xffff0000u);
    asm("cvt.rn.bf16x2.f32 %0, %1, %2;" : "=r"(lp) : "f"(v1 - h1), "f"(v0 - h0));
    h = hp; l = lp;
}
__device__ __forceinline__ void mma16(float* d, const uint32_t* a, const uint32_t* b) {
    asm volatile(
        "mma.sync.aligned.m16n8k16.row.col.f32.bf16.bf16.f32 "
        "{%0,%1,%2,%3},{%4,%5,%6,%7},{%8,%9},{%0,%1,%2,%3};"
        : "+f"(d[0]), "+f"(d[1]), "+f"(d[2]), "+f"(d[3])
        : "r"(a[0]), "r"(a[1]), "r"(a[2]), "r"(a[3]), "r"(b[0]), "r"(b[1]));
}

// ---------------- stage0: prep + zero + pool + misc (one launch) ----------------
#define NB_PREP 480
#define NB_ZERO 96
#define NB_POOL (BB*EE)
#define NB_MISC (BB + NRR)
#define B_ZERO  NB_PREP
#define B_POOL  (B_ZERO + NB_ZERO)
#define B_MISC  (B_POOL + NB_POOL)
#define NB_STAGE0 (B_MISC + NB_MISC)

__global__ __launch_bounds__(256) void stage0_kernel(
        const float* __restrict__ seq,
        const int* __restrict__ starts,
        const int* __restrict__ type_ids,
        const float* __restrict__ temb,
        const float* __restrict__ remb,
        const float* __restrict__ W1,
        const float* __restrict__ W2,
        const float* __restrict__ Wr1,
        const float* __restrict__ br1) {
    __shared__ float4 sbuf4[1730];          // 27.7 KB, aliased per branch
    float* sbuf = (float*)sbuf4;
    int blk = blockIdx.x;
    int t = threadIdx.x;

    if (blk < NB_PREP) {
        // ---- weight pre-split ----
        int idx = blk*256 + t;
        if (idx < 98304) {
            int kp = idx >> 8, n = idx & 255;
            uint32_t h, l;
            split2(W1[(size_t)(2*kp)*F1 + n], W1[(size_t)(2*kp+1)*F1 + n], h, l);
            g_W1H[idx] = h; g_W1L[idx] = l;
        } else if (idx < 106496) {
            int j = idx - 98304;
            int kp = j >> 6, n = j & 63;
            uint32_t h, l;
            split2(W2[(size_t)(2*kp)*DD2 + n], W2[(size_t)(2*kp+1)*DD2 + n], h, l);
            g_W2H[j] = h; g_W2L[j] = l;
        } else {
            int j = idx - 106496;
            int kp = j >> 9, n = j & 511;
            int col = n & 255;
            int base = (n < 256) ? 0 : 64;
            uint32_t h, l;
            split2(Wr1[(size_t)(base + 2*kp)*256 + col],
                   Wr1[(size_t)(base + 2*kp + 1)*256 + col], h, l);
            g_WpH[j] = h; g_WpL[j] = l;
        }
    } else if (blk < B_POOL) {
        // ---- zero s/d accumulators ----
        int j = (blk - B_ZERO)*256 + t;
        if (j < 8192) g_s1[j] = 0.f;
        else if (j < 16384) g_d1[j - 8192] = 0.f;
        else if (j < 20480) g_s2[j - 16384] = 0.f;
        else g_d2[j - 20480] = 0.f;
    } else if (blk < B_MISC) {
        // ---- entity pooling + type embedding ----
        int be = blk - B_POOL;
        int b = be >> 7;
        float* toks = sbuf;
        float* colsum = sbuf + WW*HH;
        float* logits = sbuf + WW*HH + HH;

        int start = starts[be];
        const float4* base4 = (const float4*)(seq + ((size_t)b*SS + start)*HH);
        #pragma unroll
        for (int i = 0; i < 6; i++) sbuf4[t + i*256] = base4[t + i*256];
        __syncthreads();

        for (int h = t; h < HH; h += 256) {
            float cs = 0.f;
            #pragma unroll
            for (int w = 0; w < WW; w++) cs += toks[w*HH + h];
            colsum[h] = cs;
        }
        __syncthreads();

        int warp = t >> 5, lane = t & 31;
        {
            float acc = 0.f;
            for (int h = lane; h < HH; h += 32) acc += toks[warp*HH + h] * colsum[h];
            #pragma unroll
            for (int off = 16; off > 0; off >>= 1) acc += __shfl_xor_sync(0xffffffffu, acc, off);
            if (lane == 0) logits[warp] = acc * 0.125f;
        }
        __syncthreads();

        float m = logits[0];
        #pragma unroll
        for (int w = 1; w < WW; w++) m = fmaxf(m, logits[w]);
        float ex[WW]; float sum = 0.f;
        #pragma unroll
        for (int w = 0; w < WW; w++) { ex[w] = __expf(logits[w] - m); sum += ex[w]; }
        float inv = 1.f / sum;

        int type = type_ids[be];
        const float* te = temb + (size_t)type*HH;
        for (int h = t; h < HH; h += 256) {
            float p = 0.f;
            #pragma unroll
            for (int w = 0; w < WW; w++) p += ex[w] * toks[w*HH + h];
            g_x0[(size_t)be*HH + h] = p*inv + te[h];
        }
    } else {
        // ---- cls (+br1) / rel projections ----
        int mblk = blk - B_MISC;
        int c = t;
        if (mblk < BB) {
            int b = mblk;
            float* cls = sbuf;
            for (int h = c; h < HH; h += 256) cls[h] = seq[(size_t)b*SS*HH + h];
            __syncthreads();
            float acc = br1[c];
            const float* w = Wr1 + (size_t)160*256 + c;
            for (int h = 0; h < HH; h++) acc += cls[h] * w[(size_t)h*256];
            g_cls[b*256 + c] = acc;
        } else {
            int r = mblk - BB;
            float* rv = sbuf;
            if (c < RDD) rv[c] = remb[r*RDD + c];
            __syncthreads();
            float acc = 0.f;
            #pragma unroll
            for (int k = 0; k < RDD; k++) acc += rv[k] * Wr1[(size_t)(128 + k)*256 + c];
            g_rel[r*256 + c] = acc;
        }
    }
}

#define SA 20   // A smem stride (u32)
#define SBp 72  // B smem stride (u32)

// ---------------- GEMM with pre-packed B; double-buffered smem; s/d epilogue ------
__global__ __launch_bounds__(256) void bf16_gemm_pb(
        const float* __restrict__ A,
        const uint32_t* __restrict__ BH, const uint32_t* __restrict__ BL,
        float* __restrict__ C, int M, int N, int K, int lda,
        const float* __restrict__ a_src, const float* __restrict__ a_dst,
        float* __restrict__ s_out, float* __restrict__ d_out,
        int D, int Hh) {
    __shared__ uint32_t AsH[2][64][SA], AsL[2][64][SA];
    __shared__ uint32_t BsH[2][16][SBp], BsL[2][16][SBp];

    int tid = threadIdx.x;
    int wid = tid >> 5, lane = tid & 31;
    int g = lane >> 2, ti = lane & 3;
    int warp_m = wid >> 2, warp_n = wid & 3;
    int m0 = blockIdx.y * 64, n0 = blockIdx.x * 64;

    int ar = tid >> 3, aq = tid & 7;        // A: rows ar, ar+32; col group aq*4
    int br = tid >> 4, bn = (tid & 15) * 4; // B: k-pair row br, cols bn..bn+3

    const float* Ap0 = A + (size_t)(m0 + ar)*lda + aq*4;
    const float* Ap1 = A + (size_t)(m0 + ar + 32)*lda + aq*4;
    const uint32_t* Bbase = BH + (size_t)br*N + n0 + bn;
    const uint32_t* Lbase = BL + (size_t)br*N + n0 + bn;

    // prefetch chunk 0 into registers
    float4 a0 = *(const float4*)Ap0;
    float4 a1 = *(const float4*)Ap1;
    uint4 bhv = *(const uint4*)Bbase;
    uint4 blv = *(const uint4*)Lbase;

    // stage chunk 0 -> buffer 0
    {
        uint32_t h0, l0, h1, l1;
        split2(a0.x, a0.y, h0, l0);
        split2(a0.z, a0.w, h1, l1);
        AsH[0][ar][2*aq]   = h0; AsH[0][ar][2*aq+1] = h1;
        AsL[0][ar][2*aq]   = l0; AsL[0][ar][2*aq+1] = l1;
        split2(a1.x, a1.y, h0, l0);
        split2(a1.z, a1.w, h1, l1);
        AsH[0][ar+32][2*aq]   = h0; AsH[0][ar+32][2*aq+1] = h1;
        AsL[0][ar+32][2*aq]   = l0; AsL[0][ar+32][2*aq+1] = l1;
        *(uint4*)&BsH[0][br][bn] = bhv;
        *(uint4*)&BsL[0][br][bn] = blv;
    }
    __syncthreads();

    float acc[2][2][4] = {};
    int nch = K >> 5;

    for (int ic = 0; ic < nch; ic++) {
        int cur = ic & 1;
        bool more = (ic + 1 < nch);
        if (more) {
            int kc = (ic + 1) * 32;
            a0 = *(const float4*)(Ap0 + kc);
            a1 = *(const float4*)(Ap1 + kc);
            size_t off = (size_t)(kc >> 1)*N;
            bhv = *(const uint4*)(Bbase + off);
            blv = *(const uint4*)(Lbase + off);
        }

        #pragma unroll
        for (int s = 0; s < 2; s++) {
            int ab = s*8;
            uint32_t aH[2][4], aL[2][4], bH[2][2], bL[2][2];
            #pragma unroll
            for (int mt = 0; mt < 2; mt++) {
                int rm = warp_m*32 + mt*16;
                aH[mt][0] = AsH[cur][rm + g    ][ab + ti    ];
                aH[mt][1] = AsH[cur][rm + g + 8][ab + ti    ];
                aH[mt][2] = AsH[cur][rm + g    ][ab + ti + 4];
                aH[mt][3] = AsH[cur][rm + g + 8][ab + ti + 4];
                aL[mt][0] = AsL[cur][rm + g    ][ab + ti    ];
                aL[mt][1] = AsL[cur][rm + g + 8][ab + ti    ];
                aL[mt][2] = AsL[cur][rm + g    ][ab + ti + 4];
                aL[mt][3] = AsL[cur][rm + g + 8][ab + ti + 4];
            }
            #pragma unroll
            for (int nt = 0; nt < 2; nt++) {
                int cn = warp_n*16 + nt*8;
                bH[nt][0] = BsH[cur][ab + ti    ][cn + g];
                bH[nt][1] = BsH[cur][ab + ti + 4][cn + g];
                bL[nt][0] = BsL[cur][ab + ti    ][cn + g];
                bL[nt][1] = BsL[cur][ab + ti + 4][cn + g];
            }
            #pragma unroll
            for (int mt = 0; mt < 2; mt++)
                #pragma unroll
                for (int nt = 0; nt < 2; nt++) {
                    mma16(acc[mt][nt], aH[mt], bL[nt]);
                    mma16(acc[mt][nt], aL[mt], bH[nt]);
                    mma16(acc[mt][nt], aH[mt], bH[nt]);
                }
        }

        if (more) {
            int nxt = cur ^ 1;
            uint32_t h0, l0, h1, l1;
            split2(a0.x, a0.y, h0, l0);
            split2(a0.z, a0.w, h1, l1);
            AsH[nxt][ar][2*aq]   = h0; AsH[nxt][ar][2*aq+1] = h1;
            AsL[nxt][ar][2*aq]   = l0; AsL[nxt][ar][2*aq+1] = l1;
            split2(a1.x, a1.y, h0, l0);
            split2(a1.z, a1.w, h1, l1);
            AsH[nxt][ar+32][2*aq]   = h0; AsH[nxt][ar+32][2*aq+1] = h1;
            AsL[nxt][ar+32][2*aq]   = l0; AsL[nxt][ar+32][2*aq+1] = l1;
            *(uint4*)&BsH[nxt][br][bn] = bhv;
            *(uint4*)&BsL[nxt][br][bn] = blv;
        }
        __syncthreads();
    }

    #pragma unroll
    for (int mt = 0; mt < 2; mt++) {
        int rm = m0 + warp_m*32 + mt*16;
        #pragma unroll
        for (int nt = 0; nt < 2; nt++) {
            int cn = n0 + warp_n*16 + nt*8;
            float* c0 = C + (size_t)(rm + g)*N + cn + 2*ti;
            float* c2 = C + (size_t)(rm + g + 8)*N + cn + 2*ti;
            c0[0] = acc[mt][nt][0]; c0[1] = acc[mt][nt][1];
            c2[0] = acc[mt][nt][2]; c2[1] = acc[mt][nt][3];
        }
    }

    // ---- fused s/d dot epilogue ----
    if (D) {
        int head = n0 / D;
        const float* as = a_src + head*D;
        const float* ad = a_dst + head*D;
        int cbase = n0 & (D-1);
        float sv[4] = {0.f,0.f,0.f,0.f}, dv[4] = {0.f,0.f,0.f,0.f};
        #pragma unroll
        for (int nt = 0; nt < 2; nt++) {
            int c = cbase + warp_n*16 + nt*8 + 2*ti;
            float w0s = as[c], w1s = as[c+1];
            float w0d = ad[c], w1d = ad[c+1];
            #pragma unroll
            for (int mt = 0; mt < 2; mt++) {
                sv[mt*2+0] += acc[mt][nt][0]*w0s + acc[mt][nt][1]*w1s;
                sv[mt*2+1] += acc[mt][nt][2]*w0s + acc[mt][nt][3]*w1s;
                dv[mt*2+0] += acc[mt][nt][0]*w0d + acc[mt][nt][1]*w1d;
                dv[mt*2+1] += acc[mt][nt][2]*w0d + acc[mt][nt][3]*w1d;
            }
        }
        #pragma unroll
        for (int i = 0; i < 4; i++) {
            sv[i] += __shfl_xor_sync(0xffffffffu, sv[i], 1);
            sv[i] += __shfl_xor_sync(0xffffffffu, sv[i], 2);
            dv[i] += __shfl_xor_sync(0xffffffffu, dv[i], 1);
            dv[i] += __shfl_xor_sync(0xffffffffu, dv[i], 2);
        }
        if (ti == 0) {
            #pragma unroll
            for (int mt = 0; mt < 2; mt++)
                #pragma unroll
                for (int rr = 0; rr < 2; rr++) {
                    int grow = m0 + warp_m*32 + mt*16 + rr*8 + g;
                    int b = grow >> 7, e = grow & 127;
                    int idx = (b*Hh + head)*EE + e;
                    atomicAdd(&s_out[idx], sv[mt*2+rr]);
                    atomicAdd(&d_out[idx], dv[mt*2+rr]);
                }
        }
    }
}

// ---------------- attention GEMM: C = softmax_rows(leaky(d_i+s_j)) @ B ----------------
// K = EE = 128 fixed; double-buffered smem.
// If lnbias != nullptr (gridDim.x==1, N==64): fused bias+LN+elu epilogue to xout.
__global__ __launch_bounds__(256) void attn_gemm(
        const float* __restrict__ s_in, const float* __restrict__ d_in,
        const float* __restrict__ Bm, float* __restrict__ C,
        int N, int ldb, int ldc,
        int Hh, long sBb, long sBh, long sCb, long sCh,
        const float* __restrict__ lnbias, const float* __restrict__ lng,
        const float* __restrict__ lnbt, float* __restrict__ xout) {
    int bz = blockIdx.z;
    int bb = bz / Hh, hh = bz - bb*Hh;
    const float* sp = s_in + (size_t)bz*EE;
    const float* dp = d_in + (size_t)bz*EE;
    Bm += (long)bb * sBb + (long)hh * sBh;
    C  += (long)bb * sCb + (long)hh * sCh;

    __shared__ uint32_t AsH[2][64][SA], AsL[2][64][SA];
    __shared__ uint32_t BsH[2][16][SBp], BsL[2][16][SBp];
    __shared__ float s_sh[EE], d_sh[64], m_sh[64], inv_sh[64];
    __shared__ float Cs[64][68];

    int tid = threadIdx.x;
    int wid = tid >> 5, lane = tid & 31;
    int g = lane >> 2, ti = lane & 3;
    int warp_m = wid >> 2, warp_n = wid & 3;
    int m0 = blockIdx.y * 64, n0 = blockIdx.x * 64;

    int arow = tid >> 3, aq = tid & 7;
    int br = tid >> 4, bn = (tid & 15) * 4;
    const float* Bp0 = Bm + (size_t)(2*br)*ldb + n0 + bn;
    const float* Bp1 = Bm + (size_t)(2*br + 1)*ldb + n0 + bn;

    if (tid < EE) s_sh[tid] = sp[tid];
    else if (tid < EE + 64) d_sh[tid - EE] = dp[m0 + tid - EE];

    float4 b0v = *(const float4*)Bp0;
    float4 b1v = *(const float4*)Bp1;
    __syncthreads();

    #pragma unroll
    for (int rr = 0; rr < 8; rr++) {
        int i = wid*8 + rr;
        float di = d_sh[i];
        float ev[4]; float m = -1e30f;
        #pragma unroll
        for (int q = 0; q < 4; q++) {
            float e = di + s_sh[lane + q*32];
            e = fmaxf(e, 0.2f*e);
            ev[q] = e;
            m = fmaxf(m, e);
        }
        #pragma unroll
        for (int off = 16; off > 0; off >>= 1) m = fmaxf(m, __shfl_xor_sync(0xffffffffu, m, off));
        float sum = 0.f;
        #pragma unroll
        for (int q = 0; q < 4; q++) sum += __expf(ev[q] - m);
        #pragma unroll
        for (int off = 16; off > 0; off >>= 1) sum += __shfl_xor_sync(0xffffffffu, sum, off);
        if (lane == 0) { m_sh[i] = m; inv_sh[i] = 1.f / sum; }
    }
    __syncthreads();

    // stage chunk 0 -> buffer 0
    {
        float di = d_sh[arow], mi = m_sh[arow], ii = inv_sh[arow];
        int row2 = (tid + 256) >> 3;
        float di2 = d_sh[row2], mi2 = m_sh[row2], ii2 = inv_sh[row2];
        float v[4], v2[4];
        #pragma unroll
        for (int tq = 0; tq < 4; tq++) {
            float e = di + s_sh[4*aq + tq];
            e = fmaxf(e, 0.2f*e);
            v[tq] = __expf(e - mi) * ii;
            float e2 = di2 + s_sh[4*aq + tq];
            e2 = fmaxf(e2, 0.2f*e2);
            v2[tq] = __expf(e2 - mi2) * ii2;
        }
        uint32_t h0, l0, h1, l1;
        split2(v[0], v[1], h0, l0);
        split2(v[2], v[3], h1, l1);
        AsH[0][arow][2*aq] = h0; AsH[0][arow][2*aq+1] = h1;
        AsL[0][arow][2*aq] = l0; AsL[0][arow][2*aq+1] = l1;
        split2(v2[0], v2[1], h0, l0);
        split2(v2[2], v2[3], h1, l1);
        AsH[0][row2][2*aq] = h0; AsH[0][row2][2*aq+1] = h1;
        AsL[0][row2][2*aq] = l0; AsL[0][row2][2*aq+1] = l1;
        uint32_t h, l;
        split2(b0v.x, b1v.x, h, l); BsH[0][br][bn+0] = h; BsL[0][br][bn+0] = l;
        split2(b0v.y, b1v.y, h, l); BsH[0][br][bn+1] = h; BsL[0][br][bn+1] = l;
        split2(b0v.z, b1v.z, h, l); BsH[0][br][bn+2] = h; BsL[0][br][bn+2] = l;
        split2(b0v.w, b1v.w, h, l); BsH[0][br][bn+3] = h; BsL[0][br][bn+3] = l;
    }
    __syncthreads();

    float acc[2][2][4] = {};

    #pragma unroll
    for (int ic = 0; ic < 4; ic++) {
        int cur = ic & 1;
        bool more = (ic + 1 < 4);
        if (more) {
            int kc = (ic + 1) * 32;
            b0v = *(const float4*)(Bp0 + (size_t)kc*ldb);
            b1v = *(const float4*)(Bp1 + (size_t)kc*ldb);
        }

        #pragma unroll
        for (int s = 0; s < 2; s++) {
            int ab = s*8;
            uint32_t aH[2][4], aL[2][4], bH[2][2], bL[2][2];
            #pragma unroll
            for (int mt = 0; mt < 2; mt++) {
                int rm = warp_m*32 + mt*16;
                aH[mt][0] = AsH[cur][rm + g    ][ab + ti    ];
                aH[mt][1] = AsH[cur][rm + g + 8][ab + ti    ];
                aH[mt][2] = AsH[cur][rm + g    ][ab + ti + 4];
                aH[mt][3] = AsH[cur][rm + g + 8][ab + ti + 4];
                aL[mt][0] = AsL[cur][rm + g    ][ab + ti    ];
                aL[mt][1] = AsL[cur][rm + g + 8][ab + ti    ];
                aL[mt][2] = AsL[cur][rm + g    ][ab + ti + 4];
                aL[mt][3] = AsL[cur][rm + g + 8][ab + ti + 4];
            }
            #pragma unroll
            for (int nt = 0; nt < 2; nt++) {
                int cn = warp_n*16 + nt*8;
                bH[nt][0] = BsH[cur][ab + ti    ][cn + g];
                bH[nt][1] = BsH[cur][ab + ti + 4][cn + g];
                bL[nt][0] = BsL[cur][ab + ti    ][cn + g];
                bL[nt][1] = BsL[cur][ab + ti + 4][cn + g];
            }
            #pragma unroll
            for (int mt = 0; mt < 2; mt++)
                #pragma unroll
                for (int nt = 0; nt < 2; nt++) {
                    mma16(acc[mt][nt], aH[mt], bL[nt]);
                    mma16(acc[mt][nt], aL[mt], bH[nt]);
                    mma16(acc[mt][nt], aH[mt], bH[nt]);
                }
        }

        if (more) {
            int nxt = cur ^ 1;
            int kc = (ic + 1) * 32;
            float di = d_sh[arow], mi = m_sh[arow], ii = inv_sh[arow];
            int row2 = (tid + 256) >> 3;
            float di2 = d_sh[row2], mi2 = m_sh[row2], ii2 = inv_sh[row2];
            float v[4], v2[4];
            #pragma unroll
            for (int tq = 0; tq < 4; tq++) {
                float e = di + s_sh[kc + 4*aq + tq];
                e = fmaxf(e, 0.2f*e);
                v[tq] = __expf(e - mi) * ii;
                float e2 = di2 + s_sh[kc + 4*aq + tq];
                e2 = fmaxf(e2, 0.2f*e2);
                v2[tq] = __expf(e2 - mi2) * ii2;
            }
            uint32_t h0, l0, h1, l1;
            split2(v[0], v[1], h0, l0);
            split2(v[2], v[3], h1, l1);
            AsH[nxt][arow][2*aq] = h0; AsH[nxt][arow][2*aq+1] = h1;
            AsL[nxt][arow][2*aq] = l0; AsL[nxt][arow][2*aq+1] = l1;
            split2(v2[0], v2[1], h0, l0);
            split2(v2[2], v2[3], h1, l1);
            AsH[nxt][row2][2*aq] = h0; AsH[nxt][row2][2*aq+1] = h1;
            AsL[nxt][row2][2*aq] = l0; AsL[nxt][row2][2*aq+1] = l1;
            uint32_t h, l;
            split2(b0v.x, b1v.x, h, l); BsH[nxt][br][bn+0] = h; BsL[nxt][br][bn+0] = l;
            split2(b0v.y, b1v.y, h, l); BsH[nxt][br][bn+1] = h; BsL[nxt][br][bn+1] = l;
            split2(b0v.z, b1v.z, h, l); BsH[nxt][br][bn+2] = h; BsL[nxt][br][bn+2] = l;
            split2(b0v.w, b1v.w, h, l); BsH[nxt][br][bn+3] = h; BsL[nxt][br][bn+3] = l;
        }
        __syncthreads();
    }

    if (lnbias == nullptr) {
        #pragma unroll
        for (int mt = 0; mt < 2; mt++) {
            int rm = m0 + warp_m*32 + mt*16;
            #pragma unroll
            for (int nt = 0; nt < 2; nt++) {
                int cn = n0 + warp_n*16 + nt*8;
                float* c0 = C + (size_t)(rm + g)*ldc + cn + 2*ti;
                float* c2 = C + (size_t)(rm + g + 8)*ldc + cn + 2*ti;
                c0[0] = acc[mt][nt][0]; c0[1] = acc[mt][nt][1];
                c2[0] = acc[mt][nt][2]; c2[1] = acc[mt][nt][3];
            }
        }
    } else {
        // fused bias + layernorm + elu (N == 64, full row in block)
        #pragma unroll
        for (int mt = 0; mt < 2; mt++) {
            int r0 = warp_m*32 + mt*16 + g;
            #pragma unroll
            for (int nt = 0; nt < 2; nt++) {
                int cn = warp_n*16 + nt*8 + 2*ti;
                Cs[r0    ][cn] = acc[mt][nt][0]; Cs[r0    ][cn+1] = acc[mt][nt][1];
                Cs[r0 + 8][cn] = acc[mt][nt][2]; Cs[r0 + 8][cn+1] = acc[mt][nt][3];
            }
        }
        __syncthreads();
        int c = 2*lane;
        float2 bb2 = *(const float2*)(lnbias + c);
        float2 gg  = *(const float2*)(lng + c);
        float2 tt  = *(const float2*)(lnbt + c);
        #pragma unroll
        for (int rr = 0; rr < 8; rr++) {
            int r = wid*8 + rr;
            float vx = Cs[r][c]   + bb2.x;
            float vy = Cs[r][c+1] + bb2.y;
            float s = vx + vy, s2 = vx*vx + vy*vy;
            #pragma unroll
            for (int off = 16; off > 0; off >>= 1) {
                s  += __shfl_xor_sync(0xffffffffu, s,  off);
                s2 += __shfl_xor_sync(0xffffffffu, s2, off);
            }
            float mean = s * (1.f/64.f);
            float var  = s2 * (1.f/64.f) - mean*mean;
            float rstd = rsqrtf(var + 1e-5f);
            float ox = (vx - mean)*rstd*gg.x + tt.x;
            float oy = (vy - mean)*rstd*gg.y + tt.y;
            ox = ox > 0.f ? ox : expm1f(ox);
            oy = oy > 0.f ? oy : expm1f(oy);
            float2 o2v = make_float2(ox, oy);
            *(float2*)(xout + (size_t)(bz*EE + m0 + r)*64 + c) = o2v;
        }
    }
}

// ---------------- bias + layernorm + elu (256-wide rows), warp-per-row ----------------
__global__ void ln256_kernel(const float* __restrict__ in,
                             const float* __restrict__ bias,
                             const float* __restrict__ g,
                             const float* __restrict__ bt,
                             float* __restrict__ out) {
    int t = threadIdx.x;
    int row = blockIdx.x*8 + (t >> 5);
    int lane = t & 31;
    int c0 = 4*lane, c1 = 128 + 4*lane;
    const float* ir = in + (size_t)row*256;
    float4 v0 = *(const float4*)(ir + c0);
    float4 v1 = *(const float4*)(ir + c1);
    float4 b0 = *(const float4*)(bias + c0);
    float4 b1 = *(const float4*)(bias + c1);
    v0.x += b0.x; v0.y += b0.y; v0.z += b0.z; v0.w += b0.w;
    v1.x += b1.x; v1.y += b1.y; v1.z += b1.z; v1.w += b1.w;
    float s  = v0.x+v0.y+v0.z+v0.w + v1.x+v1.y+v1.z+v1.w;
    float s2 = v0.x*v0.x+v0.y*v0.y+v0.z*v0.z+v0.w*v0.w
             + v1.x*v1.x+v1.y*v1.y+v1.z*v1.z+v1.w*v1.w;
    #pragma unroll
    for (int off = 16; off > 0; off >>= 1) {
        s  += __shfl_xor_sync(0xffffffffu, s,  off);
        s2 += __shfl_xor_sync(0xffffffffu, s2, off);
    }
    float mean = s * (1.f/256.f);
    float var  = s2 * (1.f/256.f) - mean*mean;
    float r = rsqrtf(var + 1e-5f);
    float4 g0 = *(const float4*)(g + c0);
    float4 g1 = *(const float4*)(g + c1);
    float4 t0 = *(const float4*)(bt + c0);
    float4 t1 = *(const float4*)(bt + c1);
    float4 o0, o1;
    o0.x = (v0.x-mean)*r*g0.x + t0.x; o0.y = (v0.y-mean)*r*g0.y + t0.y;
    o0.z = (v0.z-mean)*r*g0.z + t0.z; o0.w = (v0.w-mean)*r*g0.w + t0.w;
    o1.x = (v1.x-mean)*r*g1.x + t1.x; o1.y = (v1.y-mean)*r*g1.y + t1.y;
    o1.z = (v1.z-mean)*r*g1.z + t1.z; o1.w = (v1.w-mean)*r*g1.w + t1.w;
    o0.x = o0.x > 0.f ? o0.x : expm1f(o0.x); o0.y = o0.y > 0.f ? o0.y : expm1f(o0.y);
    o0.z = o0.z > 0.f ? o0.z : expm1f(o0.z); o0.w = o0.w > 0.f ? o0.w : expm1f(o0.w);
    o1.x = o1.x > 0.f ? o1.x : expm1f(o1.x); o1.y = o1.y > 0.f ? o1.y : expm1f(o1.y);
    o1.z = o1.z > 0.f ? o1.z : expm1f(o1.z); o1.w = o1.w > 0.f ? o1.w : expm1f(o1.w);
    float* orow = out + (size_t)row*256;
    *(float4*)(orow + c0) = o0;
    *(float4*)(orow + c1) = o1;
}

// ---------------- final pair scores ----------------
__global__ void pair_kernel(const int* __restrict__ pidx,
                            const int* __restrict__ rids,
                            const float* __restrict__ p,
                            const float* __restrict__ relp,
                            const float* __restrict__ clsp,
                            const float* __restrict__ Wr2,
                            const float* __restrict__ br2,
                            float* __restrict__ out) {
    int g = (blockIdx.x * blockDim.x + threadIdx.x) >> 5;
    int lane = threadIdx.x & 31;
    int b = g / PP, pp = g % PP;
    int pi = pidx[(b*PP + pp)*2 + 0];
    int pj = pidx[(b*PP + pp)*2 + 1];
    int r  = rids[b*PP + pp];
    const float* a1 = p + (size_t)(b*EE + pi)*512;
    const float* a2 = p + (size_t)(b*EE + pj)*512 + 256;
    const float* ar = relp + r*256;
    const float* ac = clsp + b*256;
    float acc = 0.f;
    #pragma unroll
    for (int q = 0; q < 8; q++) {
        int c = lane + q*32;
        float v = a1[c] + a2[c] + ar[c] + ac[c];
        v = fmaxf(v, 0.f);
        acc += v * Wr2[c];
    }
    #pragma unroll
    for (int off = 16; off > 0; off >>= 1) acc += __shfl_xor_sync(0xffffffffu, acc, off);
    if (lane == 0) out[b*PP + pp] = acc + br2[0];
}

// ---------------- launch ----------------
extern "C" void kernel_launch(void* const* d_in, const int* in_sizes, int n_in,
                              void* d_out, int out_size) {
    const float* seq      = (const float*)d_in[0];
    const int*   starts   = (const int*)  d_in[1];
    const int*   type_ids = (const int*)  d_in[2];
    const int*   pair_idx = (const int*)  d_in[3];
    const int*   rel_ids  = (const int*)  d_in[4];
    const float* temb     = (const float*)d_in[5];
    const float* remb     = (const float*)d_in[6];
    const float* W1       = (const float*)d_in[7];
    const float* a_src1   = (const float*)d_in[8];
    const float* a_dst1   = (const float*)d_in[9];
    const float* b1       = (const float*)d_in[10];
    const float* ln1_g    = (const float*)d_in[11];
    const float* ln1_b    = (const float*)d_in[12];
    const float* W2       = (const float*)d_in[13];
    const float* a_src2   = (const float*)d_in[14];
    const float* a_dst2   = (const float*)d_in[15];
    const float* b2       = (const float*)d_in[16];
    const float* ln2_g    = (const float*)d_in[17];
    const float* ln2_b    = (const float*)d_in[18];
    const float* Wr1      = (const float*)d_in[19];
    const float* br1      = (const float*)d_in[20];
    const float* Wr2      = (const float*)d_in[21];
    const float* br2      = (const float*)d_in[22];
    float* out = (float*)d_out;

    float *x0, *h1, *s1, *d1, *o1, *x1, *h2, *s2, *d2, *x2, *p, *clsp, *relp;
    uint32_t *W1H, *W1L, *W2H, *W2L, *WpH, *WpL;
    cudaGetSymbolAddress((void**)&x0,  g_x0);
    cudaGetSymbolAddress((void**)&h1,  g_h1);
    cudaGetSymbolAddress((void**)&s1,  g_s1);
    cudaGetSymbolAddress((void**)&d1,  g_d1);
    cudaGetSymbolAddress((void**)&o1,  g_o1);
    cudaGetSymbolAddress((void**)&x1,  g_x1);
    cudaGetSymbolAddress((void**)&h2,  g_h2);
    cudaGetSymbolAddress((void**)&s2,  g_s2);
    cudaGetSymbolAddress((void**)&d2,  g_d2);
    cudaGetSymbolAddress((void**)&x2,  g_x2);
    cudaGetSymbolAddress((void**)&p,   g_p);
    cudaGetSymbolAddress((void**)&clsp, g_cls);
    cudaGetSymbolAddress((void**)&relp, g_rel);
    cudaGetSymbolAddress((void**)&W1H, g_W1H);
    cudaGetSymbolAddress((void**)&W1L, g_W1L);
    cudaGetSymbolAddress((void**)&W2H, g_W2H);
    cudaGetSymbolAddress((void**)&W2L, g_W2L);
    cudaGetSymbolAddress((void**)&WpH, g_WpH);
    cudaGetSymbolAddress((void**)&WpL, g_WpL);

    // 1. stage0: prep + zero + pool + misc
    stage0_kernel<<<NB_STAGE0, 256>>>(seq, starts, type_ids, temb, remb,
                                      W1, W2, Wr1, br1);

    // 2. h1 = x0 @ W1, s1/d1 fused
    bf16_gemm_pb<<<dim3(4, 64), 256>>>(x0, W1H, W1L, h1, BB*EE, F1, HH, HH,
                                       a_src1, a_dst1, s1, d1, DD1, HEADS1);

    // 3. o1 = softmax(leaky(d+s)) @ h1, per (b,head)
    attn_gemm<<<dim3(2, 2, BB*HEADS1), 256>>>(s1, d1, h1, o1,
                                              DD1, F1, F1, HEADS1,
                                              (long)EE*F1, DD1, (long)EE*F1, DD1,
                                              nullptr, nullptr, nullptr, nullptr);

    // 4. x1 = elu(ln(o1 + b1))
    ln256_kernel<<<BB*EE/8, 256>>>(o1, b1, ln1_g, ln1_b, x1);

    // 5. h2 = x1 @ W2, s2/d2 fused
    bf16_gemm_pb<<<dim3(1, 64), 256>>>(x1, W2H, W2L, h2, BB*EE, DD2, F1, F1,
                                       a_src2, a_dst2, s2, d2, DD2, 1);

    // 6. x2 = elu(ln(softmax @ h2 + b2)) — attn + LN fused
    attn_gemm<<<dim3(1, 2, BB), 256>>>(s2, d2, h2, x2,
                                       DD2, DD2, DD2, 1,
                                       (long)EE*DD2, 0, (long)EE*DD2, 0,
                                       b2, ln2_g, ln2_b, x2);

    // 7. pair projections: (4096,64)@(64,512) -> p=[p1|p2]
    bf16_gemm_pb<<<dim3(8, 64), 256>>>(x2, WpH, WpL, p, BB*EE, 512, DD2, DD2,
                                       nullptr, nullptr, nullptr, nullptr, 0, 1);

    // 8. pair scores
    pair_kernel<<<(BB*PP)/8, 256>>>(pair_idx, rel_ids, p, relp, clsp,
                                    Wr2, br2, out);
}